// round 13
// baseline (speedup 1.0000x reference)
#include <cuda_runtime.h>
#include <cuda_fp16.h>
#include <math_constants.h>
#include <cstdint>

#define BB 8
#define SS 4096
#define DD 512
#define MEM 256
#define HID 1024
#define KK 768
#define NF 8192
#define NH 4096          // NF/2

// ---------------- device scratch ----------------
__device__ float  g_u[BB * SS];
__device__ float2 g_Ufft[BB * NF];
__device__ float2 g_Hfft[(MEM / 2) * NF];          // packed pair spectra
__device__ float2 g_tw[NH];
__device__ half   g_mH[(size_t)BB * MEM * SS];     // [b][k][s] fp16 (k < 256)
__device__ half   g_xH[(size_t)BB * SS * DD];      // [b][s][d] fp16
__device__ half   g_W16[(size_t)HID * KK];         // [h][k] fp16

// ---------------- capture-fork resources (host objects, created pre-main) ----------------
struct GxStreams {
    cudaStream_t s2;
    cudaEvent_t e1, e2;
    GxStreams() {
        cudaStreamCreateWithFlags(&s2, cudaStreamNonBlocking);
        cudaEventCreateWithFlags(&e1, cudaEventDisableTiming);
        cudaEventCreateWithFlags(&e2, cudaEventDisableTiming);
    }
};
static GxStreams gs;

__device__ __forceinline__ uint32_t s2u(const void* p) {
    uint32_t a;
    asm("{ .reg .u64 t; cvta.to.shared.u64 t, %1; cvt.u32.u64 %0, t; }" : "=r"(a) : "l"(p));
    return a;
}

__device__ __forceinline__ float2 cmul(float2 a, float2 b) {
    return make_float2(a.x * b.x - a.y * b.y, a.x * b.y + a.y * b.x);
}
__device__ __forceinline__ float2 cadd(float2 a, float2 b) { return make_float2(a.x + b.x, a.y + b.y); }
__device__ __forceinline__ float2 csub(float2 a, float2 b) { return make_float2(a.x - b.x, a.y - b.y); }

#define RT2 0.70710678118654752f

// ================= radix-2^3 FFT cores (512 threads, X[NF] in smem) =================
__device__ __forceinline__ void fft_fwd_core(float2* X, int tid) {
    #pragma unroll
    for (int p = 0; p < 4; p++) {
        const int m  = 4096 >> (3 * p);
        const int m4 = m >> 2;
        const int st = 4096 / m;
        #pragma unroll
        for (int qq = 0; qq < 2; qq++) {
            int q = tid + qq * 512;
            int jj = q & (m4 - 1);
            int i = (q / m4) * 2 * m + jj;
            float2 P[8];
            #pragma unroll
            for (int k = 0; k < 8; k++) P[k] = X[i + k * m4];
            float2 w1 = g_tw[jj * st];
            float2 w2 = g_tw[jj * st * 2];
            float2 w4 = g_tw[jj * st * 4];
            float2 E[4];
            E[0] = w1;
            E[1] = make_float2(RT2 * (w1.x + w1.y), RT2 * (w1.y - w1.x));
            E[2] = make_float2(w1.y, -w1.x);
            E[3] = make_float2(RT2 * (w1.y - w1.x), -RT2 * (w1.x + w1.y));
            #pragma unroll
            for (int o = 0; o < 4; o++) {
                float2 t = csub(P[o], P[o + 4]);
                P[o] = cadd(P[o], P[o + 4]);
                P[o + 4] = cmul(t, E[o]);
            }
            float2 f1 = make_float2(w2.y, -w2.x);
            #pragma unroll
            for (int base = 0; base < 8; base += 4) {
                float2 t0 = csub(P[base], P[base + 2]);
                P[base] = cadd(P[base], P[base + 2]);
                P[base + 2] = cmul(t0, w2);
                float2 t1 = csub(P[base + 1], P[base + 3]);
                P[base + 1] = cadd(P[base + 1], P[base + 3]);
                P[base + 3] = cmul(t1, f1);
            }
            #pragma unroll
            for (int base = 0; base < 8; base += 2) {
                float2 t = csub(P[base], P[base + 1]);
                P[base] = cadd(P[base], P[base + 1]);
                P[base + 1] = cmul(t, w4);
            }
            #pragma unroll
            for (int k = 0; k < 8; k++) X[i + k * m4] = P[k];
        }
        __syncthreads();
    }
    #pragma unroll
    for (int qq = 0; qq < 8; qq++) {
        int t = tid + qq * 512;
        int i0 = 2 * t;
        float2 a = X[i0], b = X[i0 + 1];
        X[i0]     = cadd(a, b);
        X[i0 + 1] = csub(a, b);
    }
    __syncthreads();
}

__device__ __forceinline__ void fft_inv_core(float2* X, int tid) {
    #pragma unroll
    for (int p = 0; p < 4; p++) {
        const int m  = 2 << (3 * p);
        const int st = 4096 / m;
        #pragma unroll
        for (int qq = 0; qq < 2; qq++) {
            int g = tid + qq * 512;
            int jj = g & (m - 1);
            int i = (g / m) * 8 * m + jj;
            float2 P[8];
            #pragma unroll
            for (int k = 0; k < 8; k++) P[k] = X[i + k * m];
            float2 wa = g_tw[jj * st];
            float2 w1c = make_float2(wa.x, -wa.y);
            float2 wb = g_tw[jj * (st >> 1)];
            float2 w2c = make_float2(wb.x, -wb.y);
            float2 wc = g_tw[jj * (st >> 2)];
            float2 w4c = make_float2(wc.x, -wc.y);
            #pragma unroll
            for (int base = 0; base < 8; base += 2) {
                float2 t = cmul(P[base + 1], w1c);
                P[base + 1] = csub(P[base], t);
                P[base] = cadd(P[base], t);
            }
            float2 f1 = make_float2(-w2c.y, w2c.x);
            #pragma unroll
            for (int base = 0; base < 8; base += 4) {
                float2 t0 = cmul(P[base + 2], w2c);
                P[base + 2] = csub(P[base], t0);
                P[base] = cadd(P[base], t0);
                float2 t1 = cmul(P[base + 3], f1);
                P[base + 3] = csub(P[base + 1], t1);
                P[base + 1] = cadd(P[base + 1], t1);
            }
            float2 G[4];
            G[0] = w4c;
            G[1] = make_float2(RT2 * (w4c.x - w4c.y), RT2 * (w4c.x + w4c.y));
            G[2] = make_float2(-w4c.y, w4c.x);
            G[3] = make_float2(-RT2 * (w4c.x + w4c.y), RT2 * (w4c.x - w4c.y));
            #pragma unroll
            for (int o = 0; o < 4; o++) {
                float2 t = cmul(P[o + 4], G[o]);
                P[o + 4] = csub(P[o], t);
                P[o] = cadd(P[o], t);
            }
            #pragma unroll
            for (int k = 0; k < 8; k++) X[i + k * m] = P[k];
        }
        __syncthreads();
    }
}

// ---------------- fused prologue: u + x->fp16, W->fp16, twiddles (one launch) ----------------
__global__ void k_ux(const float* __restrict__ x, const float* __restrict__ w,
                     const float* __restrict__ b0, const float* __restrict__ W) {
    int blk = blockIdx.x;
    int tid = threadIdx.x;       // 128
    if (blk < BB * SS) {
        int r = blk;             // b*S + t
        const float4* xv = reinterpret_cast<const float4*>(x) + (size_t)r * 128;
        const float4* wv = reinterpret_cast<const float4*>(w);
        float4 a = xv[tid], ww = wv[tid];
        half2 h0 = __floats2half2_rn(a.x, a.y);
        half2 h1 = __floats2half2_rn(a.z, a.w);
        uint2 pk;
        pk.x = *reinterpret_cast<uint32_t*>(&h0);
        pk.y = *reinterpret_cast<uint32_t*>(&h1);
        *reinterpret_cast<uint2*>(g_xH + (size_t)r * DD + tid * 4) = pk;
        float p = a.x * ww.x + a.y * ww.y + a.z * ww.z + a.w * ww.w;
        __shared__ float red[128];
        red[tid] = p;
        __syncthreads();
        if (tid < 64) red[tid] += red[tid + 64];
        __syncthreads();
        if (tid < 32) {
            float v = red[tid] + red[tid + 32];
            #pragma unroll
            for (int o = 16; o; o >>= 1) v += __shfl_down_sync(0xffffffffu, v, o);
            if (tid == 0) g_u[r] = fmaxf(v + b0[0], 0.f);
        }
    } else if (blk < BB * SS + 768) {
        size_t i = ((size_t)(blk - BB * SS) * 128 + tid) * 8;
        const float4* src = reinterpret_cast<const float4*>(W + i);
        float4 v0 = src[0], v1 = src[1];
        half2 h[4];
        h[0] = __floats2half2_rn(v0.x, v0.y);
        h[1] = __floats2half2_rn(v0.z, v0.w);
        h[2] = __floats2half2_rn(v1.x, v1.y);
        h[3] = __floats2half2_rn(v1.z, v1.w);
        *reinterpret_cast<uint4*>(g_W16 + i) = *reinterpret_cast<uint4*>(h);
    } else {
        int r = (blk - BB * SS - 768) * 128 + tid;
        float s, c;
        sincosf(-CUDART_PI_F * (float)r / (float)NH, &s, &c);
        g_tw[r] = make_float2(c, s);
    }
}

// ---------------- merged forward FFTs: blocks 0..127 = H pairs, 128..135 = u rows ----------------
__global__ void k_fft_fwd_all(const float* __restrict__ H) {
    extern __shared__ float2 X[];
    int tid = threadIdx.x;
    int blk = blockIdx.x;
    if (blk < 128) {
        const float* h1 = H + (size_t)(2 * blk) * SS;
        const float* h2 = H + (size_t)(2 * blk + 1) * SS;
        for (int j = tid; j < NF; j += 512)
            X[j] = (j < SS) ? make_float2(h1[j], h2[j]) : make_float2(0.f, 0.f);
        __syncthreads();
        fft_fwd_core(X, tid);
        float2* dst = g_Hfft + (size_t)blk * NF;
        for (int j = tid; j < NF; j += 512) dst[j] = X[j];
    } else {
        int b = blk - 128;
        const float* src = g_u + (size_t)b * SS;
        for (int j = tid; j < NF; j += 512)
            X[j] = make_float2(j < SS ? src[j] : 0.f, 0.f);
        __syncthreads();
        fft_fwd_core(X, tid);
        float2* dst = g_Ufft + (size_t)b * NF;
        for (int j = tid; j < NF; j += 512) dst[j] = X[j];
    }
}

// ---------------- product (+ fused distance-1 stage) + inverse FFT -> fp16 m ----------------
__global__ void k_conv() {
    extern __shared__ float2 X[];
    int tid = threadIdx.x;
    int kp = blockIdx.x, b = blockIdx.y;
    const float2* U  = g_Ufft + (size_t)b * NF;
    const float2* Hp = g_Hfft + (size_t)kp * NF;
    for (int t = tid; t < NH; t += 512) {
        int j0 = 2 * t;
        float2 a = cmul(U[j0], Hp[j0]);
        float2 bb = cmul(U[j0 + 1], Hp[j0 + 1]);
        X[j0]     = cadd(a, bb);
        X[j0 + 1] = csub(a, bb);
    }
    __syncthreads();
    fft_inv_core(X, tid);
    half* d1 = g_mH + ((size_t)b * MEM + 2 * kp) * SS;
    half* d2 = d1 + SS;
    const float inv = 1.f / NF;
    for (int s = 2 * tid; s < SS; s += 1024) {
        float2 v0 = X[s], v1 = X[s + 1];
        *reinterpret_cast<half2*>(d1 + s) = __floats2half2_rn(v0.x * inv, v1.x * inv);
        *reinterpret_cast<half2*>(d2 + s) = __floats2half2_rn(v0.y * inv, v1.y * inv);
    }
}

// ================= split HMMA GEMM =================
// Common: CTA 128(s) x 128(h), 128 threads, 4 warps (2m x 2n), warp tile 64x64,
// 3-stage cp.async pipeline, one __syncthreads per k-iter.
#define PAD 40
#define TSTR 136
#define STAGE 5120               // halfs per stage buffer (A and B each)
#define GSMEM (6 * STAGE * 2)    // bytes: 3 A stages + 3 B stages

#define MMA_STEP(amv, bmv, accv)                                              \
    asm volatile(                                                             \
        "mma.sync.aligned.m16n8k16.row.col.f32.f16.f16.f32 "                  \
        "{%0,%1,%2,%3}, {%4,%5,%6,%7}, {%8,%9}, {%0,%1,%2,%3};"               \
        : "+f"((accv)[0]), "+f"((accv)[1]), "+f"((accv)[2]), "+f"((accv)[3])  \
        : "r"((amv)[0]), "r"((amv)[1]), "r"((amv)[2]), "r"((amv)[3]),         \
          "r"((bmv)[0]), "r"((bmv)[1]))

// ---- phase 1: x-part (K = 512), writes RAW partial sums to out ----
__global__ __launch_bounds__(128, 3) void k_gemm_x(float* __restrict__ out) {
    extern __shared__ __align__(16) half smg[];
    int tid = threadIdx.x;
    int lane = tid & 31, warp = tid >> 5;
    int wm = warp & 1, wn = warp >> 1;
    int s0 = blockIdx.x * 128, h0 = blockIdx.y * 128, b = blockIdx.z;

    const half* Xg = g_xH + ((size_t)b * SS + s0) * DD;  // [s][d]
    const half* Bg = g_W16 + (size_t)h0 * KK + MEM;      // x columns of W
    uint32_t sA = s2u(smg);
    uint32_t sB = sA + 3 * STAGE * 2;

    float acc[4][8][4];
    #pragma unroll
    for (int mi = 0; mi < 4; mi++)
        #pragma unroll
        for (int ni = 0; ni < 8; ni++)
            #pragma unroll
            for (int q = 0; q < 4; q++) acc[mi][ni][q] = 0.f;

    auto load = [&](int kt, int buf) {
        int k0 = kt * 32;
        #pragma unroll
        for (int j = 0; j < 4; j++) {
            int idx = tid + j * 128;
            int row = idx >> 2, cc = idx & 3;
            uint32_t off = (uint32_t)(buf * STAGE + row * PAD + cc * 8) * 2;
            const half* pa = Xg + (size_t)row * DD + k0 + cc * 8;
            asm volatile("cp.async.ca.shared.global [%0], [%1], 16;" :: "r"(sA + off), "l"(pa));
            const half* pb = Bg + (size_t)row * KK + k0 + cc * 8;
            asm volatile("cp.async.ca.shared.global [%0], [%1], 16;" :: "r"(sB + off), "l"(pb));
        }
        asm volatile("cp.async.commit_group;");
    };

    load(0, 0);
    load(1, 1);
    int arow = lane & 15;
    int acol = (lane >> 4) << 3;
    int brow = ((lane >> 4) << 3) + (lane & 7);
    int bcol = lane & 8;

    const int KT = 16;
    for (int kt = 0; kt < KT; kt++) {
        int buf = kt % 3;
        if (kt + 1 < KT) asm volatile("cp.async.wait_group 1;");
        else             asm volatile("cp.async.wait_group 0;");
        __syncthreads();
        if (kt + 2 < KT) load(kt + 2, (kt + 2) % 3);
        #pragma unroll
        for (int ks = 0; ks < 32; ks += 16) {
            uint32_t am[4][4];
            #pragma unroll
            for (int mi = 0; mi < 4; mi++) {
                uint32_t a = sA + (uint32_t)(buf * STAGE + (wm * 64 + mi * 16 + arow) * PAD
                                             + ks + acol) * 2;
                asm volatile("ldmatrix.sync.aligned.m8n8.x4.shared.b16 {%0,%1,%2,%3}, [%4];"
                             : "=r"(am[mi][0]), "=r"(am[mi][1]), "=r"(am[mi][2]), "=r"(am[mi][3])
                             : "r"(a));
            }
            uint32_t bm[4][4];
            #pragma unroll
            for (int p = 0; p < 4; p++) {
                uint32_t a = sB + (uint32_t)(buf * STAGE + (wn * 64 + p * 16 + brow) * PAD
                                             + ks + bcol) * 2;
                asm volatile("ldmatrix.sync.aligned.m8n8.x4.shared.b16 {%0,%1,%2,%3}, [%4];"
                             : "=r"(bm[p][0]), "=r"(bm[p][1]), "=r"(bm[p][2]), "=r"(bm[p][3])
                             : "r"(a));
            }
            #pragma unroll
            for (int mi = 0; mi < 4; mi++)
                #pragma unroll
                for (int p = 0; p < 4; p++) {
                    MMA_STEP(am[mi], bm[p], acc[mi][2 * p]);
                    MMA_STEP(am[mi], (bm[p] + 2), acc[mi][2 * p + 1]);
                }
        }
    }

    int r = lane >> 2, c = (lane & 3) * 2;
    #pragma unroll
    for (int mi = 0; mi < 4; mi++)
        #pragma unroll
        for (int ni = 0; ni < 8; ni++) {
            int h = h0 + wn * 64 + ni * 8 + c;
            int s = s0 + wm * 64 + mi * 16 + r;
            size_t o0 = ((size_t)b * SS + s) * HID + h;
            *reinterpret_cast<float2*>(out + o0) =
                make_float2(acc[mi][ni][0], acc[mi][ni][1]);
            *reinterpret_cast<float2*>(out + o0 + 8 * HID) =
                make_float2(acc[mi][ni][2], acc[mi][ni][3]);
        }
}

// ---- phase 2: m-part (K = 256, trans path) + partial + bias + relu ----
__global__ __launch_bounds__(128, 3) void k_gemm_m(const float* __restrict__ bias,
                                                   float* __restrict__ out) {
    extern __shared__ __align__(16) half smg[];
    int tid = threadIdx.x;
    int lane = tid & 31, warp = tid >> 5;
    int wm = warp & 1, wn = warp >> 1;
    int s0 = blockIdx.x * 128, h0 = blockIdx.y * 128, b = blockIdx.z;

    const half* Mg = g_mH + (size_t)b * MEM * SS;   // [k][s]
    const half* Bg = g_W16 + (size_t)h0 * KK;       // m columns of W
    uint32_t sA = s2u(smg);
    uint32_t sB = sA + 3 * STAGE * 2;

    float acc[4][8][4];
    #pragma unroll
    for (int mi = 0; mi < 4; mi++)
        #pragma unroll
        for (int ni = 0; ni < 8; ni++)
            #pragma unroll
            for (int q = 0; q < 4; q++) acc[mi][ni][q] = 0.f;

    auto load = [&](int kt, int buf) {
        int k0 = kt * 32;
        #pragma unroll
        for (int j = 0; j < 4; j++) {
            int idx = tid + j * 128;
            int row = idx >> 4, cc = idx & 15;
            uint32_t off = (uint32_t)(buf * STAGE + row * TSTR + cc * 8) * 2;
            const half* pa = Mg + (size_t)(k0 + row) * SS + s0 + cc * 8;
            asm volatile("cp.async.ca.shared.global [%0], [%1], 16;" :: "r"(sA + off), "l"(pa));
        }
        #pragma unroll
        for (int j = 0; j < 4; j++) {
            int idx = tid + j * 128;
            int row = idx >> 2, cc = idx & 3;
            uint32_t off = (uint32_t)(buf * STAGE + row * PAD + cc * 8) * 2;
            const half* pb = Bg + (size_t)row * KK + k0 + cc * 8;
            asm volatile("cp.async.ca.shared.global [%0], [%1], 16;" :: "r"(sB + off), "l"(pb));
        }
        asm volatile("cp.async.commit_group;");
    };

    load(0, 0);
    load(1, 1);
    int tkrow = (lane & 7) + ((lane >> 4) << 3);  // trans path: k row
    int tmcol = lane & 8;                         // trans path: m offset
    int brow = ((lane >> 4) << 3) + (lane & 7);
    int bcol = lane & 8;

    const int KT = 8;
    for (int kt = 0; kt < KT; kt++) {
        int buf = kt % 3;
        if (kt + 1 < KT) asm volatile("cp.async.wait_group 1;");
        else             asm volatile("cp.async.wait_group 0;");
        __syncthreads();
        if (kt + 2 < KT) load(kt + 2, (kt + 2) % 3);
        #pragma unroll
        for (int ks = 0; ks < 32; ks += 16) {
            uint32_t am[4][4];
            #pragma unroll
            for (int mi = 0; mi < 4; mi++) {
                uint32_t a = sA + (uint32_t)(buf * STAGE + (ks + tkrow) * TSTR
                                             + wm * 64 + mi * 16 + tmcol) * 2;
                asm volatile("ldmatrix.sync.aligned.m8n8.x4.trans.shared.b16 {%0,%1,%2,%3}, [%4];"
                             : "=r"(am[mi][0]), "=r"(am[mi][1]), "=r"(am[mi][2]), "=r"(am[mi][3])
                             : "r"(a));
            }
            uint32_t bm[4][4];
            #pragma unroll
            for (int p = 0; p < 4; p++) {
                uint32_t a = sB + (uint32_t)(buf * STAGE + (wn * 64 + p * 16 + brow) * PAD
                                             + ks + bcol) * 2;
                asm volatile("ldmatrix.sync.aligned.m8n8.x4.shared.b16 {%0,%1,%2,%3}, [%4];"
                             : "=r"(bm[p][0]), "=r"(bm[p][1]), "=r"(bm[p][2]), "=r"(bm[p][3])
                             : "r"(a));
            }
            #pragma unroll
            for (int mi = 0; mi < 4; mi++)
                #pragma unroll
                for (int p = 0; p < 4; p++) {
                    MMA_STEP(am[mi], bm[p], acc[mi][2 * p]);
                    MMA_STEP(am[mi], (bm[p] + 2), acc[mi][2 * p + 1]);
                }
        }
    }

    int r = lane >> 2, c = (lane & 3) * 2;
    #pragma unroll
    for (int mi = 0; mi < 4; mi++)
        #pragma unroll
        for (int ni = 0; ni < 8; ni++) {
            int h = h0 + wn * 64 + ni * 8 + c;
            int s = s0 + wm * 64 + mi * 16 + r;
            float b0v = bias[h], b1v = bias[h + 1];
            size_t o0 = ((size_t)b * SS + s) * HID + h;
            float2 p0 = *reinterpret_cast<float2*>(out + o0);
            float2 p1 = *reinterpret_cast<float2*>(out + o0 + 8 * HID);
            *reinterpret_cast<float2*>(out + o0) =
                make_float2(fmaxf(acc[mi][ni][0] + p0.x + b0v, 0.f),
                            fmaxf(acc[mi][ni][1] + p0.y + b1v, 0.f));
            *reinterpret_cast<float2*>(out + o0 + 8 * HID) =
                make_float2(fmaxf(acc[mi][ni][2] + p1.x + b0v, 0.f),
                            fmaxf(acc[mi][ni][3] + p1.y + b1v, 0.f));
        }
}

// ---------------- tail: second output = h[:, -1, :] ----------------
__global__ void k_tail(float* __restrict__ out) {
    int b = blockIdx.x, h = threadIdx.x;
    out[(size_t)BB * SS * HID + (size_t)b * HID + h] =
        out[((size_t)b * SS + (SS - 1)) * HID + h];
}

// ---------------- launch ----------------
extern "C" void kernel_launch(void* const* d_in, const int* in_sizes, int n_in,
                              void* d_out, int out_size) {
    const float* x  = (const float*)d_in[0];   // (8, 4096, 512)
    const float* Wu = (const float*)d_in[1];   // (1, 512)
    const float* bu = (const float*)d_in[2];   // (1,)
    const float* Wh = (const float*)d_in[3];   // (1024, 768)
    const float* bh = (const float*)d_in[4];   // (1024,)
    const float* H  = (const float*)d_in[5];   // (256, 4096)
    float* out = (float*)d_out;

    cudaFuncSetAttribute(k_fft_fwd_all, cudaFuncAttributeMaxDynamicSharedMemorySize, NF * 8);
    cudaFuncSetAttribute(k_conv,        cudaFuncAttributeMaxDynamicSharedMemorySize, NF * 8);
    cudaFuncSetAttribute(k_gemm_x,      cudaFuncAttributeMaxDynamicSharedMemorySize, GSMEM);
    cudaFuncSetAttribute(k_gemm_m,      cudaFuncAttributeMaxDynamicSharedMemorySize, GSMEM);

    // prologue on the main (capture) stream
    k_ux<<<BB * SS + 768 + 32, 128>>>(x, Wu, bu, Wh);

    // fork: x-part GEMM runs concurrently with FFT + conv
    cudaEventRecord(gs.e1, 0);
    cudaStreamWaitEvent(gs.s2, gs.e1, 0);
    k_gemm_x<<<dim3(SS / 128, HID / 128, BB), 128, GSMEM, gs.s2>>>(out);
    cudaEventRecord(gs.e2, gs.s2);

    k_fft_fwd_all<<<128 + BB, 512, NF * 8>>>(H);
    k_conv<<<dim3(MEM / 2, BB), 512, NF * 8>>>();

    // join, then m-part GEMM completes the output
    cudaStreamWaitEvent(0, gs.e2, 0);
    k_gemm_m<<<dim3(SS / 128, HID / 128, BB), 128, GSMEM>>>(bh, out);
    k_tail<<<BB, HID>>>(out);
}

// round 16
// speedup vs baseline: 1.1706x; 1.1706x over previous
#include <cuda_runtime.h>
#include <cuda_fp16.h>
#include <math_constants.h>
#include <cstdint>

#define BB 8
#define SS 4096
#define DD 512
#define MEM 256
#define HID 1024
#define KK 768
#define NF 8192
#define NH 4096          // NF/2

// ---------------- device scratch ----------------
__device__ float  g_u[BB * SS];
__device__ float2 g_Ufft[BB * NF];
__device__ float2 g_Hfft[(MEM / 2) * NF];          // packed pair spectra
__device__ float2 g_tw[NH];
__device__ half   g_mH[(size_t)BB * MEM * SS];     // [b][k][s] fp16 (k < 256)
__device__ half   g_xH[(size_t)BB * SS * DD];      // [b][s][d] fp16
__device__ half   g_W16[(size_t)HID * KK];         // [h][k] fp16

__device__ __forceinline__ uint32_t s2u(const void* p) {
    uint32_t a;
    asm("{ .reg .u64 t; cvta.to.shared.u64 t, %1; cvt.u32.u64 %0, t; }" : "=r"(a) : "l"(p));
    return a;
}

__device__ __forceinline__ float2 cmul(float2 a, float2 b) {
    return make_float2(a.x * b.x - a.y * b.y, a.x * b.y + a.y * b.x);
}
__device__ __forceinline__ float2 cadd(float2 a, float2 b) { return make_float2(a.x + b.x, a.y + b.y); }
__device__ __forceinline__ float2 csub(float2 a, float2 b) { return make_float2(a.x - b.x, a.y - b.y); }

#define RT2 0.70710678118654752f

// ================= radix-2^3 FFT cores (512 threads, X[NF] in smem) =================
__device__ __forceinline__ void fft_fwd_core(float2* X, int tid) {
    #pragma unroll
    for (int p = 0; p < 4; p++) {
        const int m  = 4096 >> (3 * p);
        const int m4 = m >> 2;
        const int st = 4096 / m;
        #pragma unroll
        for (int qq = 0; qq < 2; qq++) {
            int q = tid + qq * 512;
            int jj = q & (m4 - 1);
            int i = (q / m4) * 2 * m + jj;
            float2 P[8];
            #pragma unroll
            for (int k = 0; k < 8; k++) P[k] = X[i + k * m4];
            float2 w1 = g_tw[jj * st];
            float2 w2 = g_tw[jj * st * 2];
            float2 w4 = g_tw[jj * st * 4];
            float2 E[4];
            E[0] = w1;
            E[1] = make_float2(RT2 * (w1.x + w1.y), RT2 * (w1.y - w1.x));
            E[2] = make_float2(w1.y, -w1.x);
            E[3] = make_float2(RT2 * (w1.y - w1.x), -RT2 * (w1.x + w1.y));
            #pragma unroll
            for (int o = 0; o < 4; o++) {
                float2 t = csub(P[o], P[o + 4]);
                P[o] = cadd(P[o], P[o + 4]);
                P[o + 4] = cmul(t, E[o]);
            }
            float2 f1 = make_float2(w2.y, -w2.x);
            #pragma unroll
            for (int base = 0; base < 8; base += 4) {
                float2 t0 = csub(P[base], P[base + 2]);
                P[base] = cadd(P[base], P[base + 2]);
                P[base + 2] = cmul(t0, w2);
                float2 t1 = csub(P[base + 1], P[base + 3]);
                P[base + 1] = cadd(P[base + 1], P[base + 3]);
                P[base + 3] = cmul(t1, f1);
            }
            #pragma unroll
            for (int base = 0; base < 8; base += 2) {
                float2 t = csub(P[base], P[base + 1]);
                P[base] = cadd(P[base], P[base + 1]);
                P[base + 1] = cmul(t, w4);
            }
            #pragma unroll
            for (int k = 0; k < 8; k++) X[i + k * m4] = P[k];
        }
        __syncthreads();
    }
    #pragma unroll
    for (int qq = 0; qq < 8; qq++) {
        int t = tid + qq * 512;
        int i0 = 2 * t;
        float2 a = X[i0], b = X[i0 + 1];
        X[i0]     = cadd(a, b);
        X[i0 + 1] = csub(a, b);
    }
    __syncthreads();
}

// Inverse DIT octet passes m = 2, 16, 128 (distances 2..512); the final
// m=1024 pass (1024/2048/4096) is specialized in k_conv with direct output.
__device__ __forceinline__ void fft_inv_core3(float2* X, int tid) {
    #pragma unroll
    for (int p = 0; p < 3; p++) {
        const int m  = 2 << (3 * p);
        const int st = 4096 / m;
        #pragma unroll
        for (int qq = 0; qq < 2; qq++) {
            int g = tid + qq * 512;
            int jj = g & (m - 1);
            int i = (g / m) * 8 * m + jj;
            float2 P[8];
            #pragma unroll
            for (int k = 0; k < 8; k++) P[k] = X[i + k * m];
            float2 wa = g_tw[jj * st];
            float2 w1c = make_float2(wa.x, -wa.y);
            float2 wb = g_tw[jj * (st >> 1)];
            float2 w2c = make_float2(wb.x, -wb.y);
            float2 wc = g_tw[jj * (st >> 2)];
            float2 w4c = make_float2(wc.x, -wc.y);
            #pragma unroll
            for (int base = 0; base < 8; base += 2) {
                float2 t = cmul(P[base + 1], w1c);
                P[base + 1] = csub(P[base], t);
                P[base] = cadd(P[base], t);
            }
            float2 f1 = make_float2(-w2c.y, w2c.x);
            #pragma unroll
            for (int base = 0; base < 8; base += 4) {
                float2 t0 = cmul(P[base + 2], w2c);
                P[base + 2] = csub(P[base], t0);
                P[base] = cadd(P[base], t0);
                float2 t1 = cmul(P[base + 3], f1);
                P[base + 3] = csub(P[base + 1], t1);
                P[base + 1] = cadd(P[base + 1], t1);
            }
            float2 G[4];
            G[0] = w4c;
            G[1] = make_float2(RT2 * (w4c.x - w4c.y), RT2 * (w4c.x + w4c.y));
            G[2] = make_float2(-w4c.y, w4c.x);
            G[3] = make_float2(-RT2 * (w4c.x + w4c.y), RT2 * (w4c.x - w4c.y));
            #pragma unroll
            for (int o = 0; o < 4; o++) {
                float2 t = cmul(P[o + 4], G[o]);
                P[o + 4] = csub(P[o], t);
                P[o] = cadd(P[o], t);
            }
            #pragma unroll
            for (int k = 0; k < 8; k++) X[i + k * m] = P[k];
        }
        __syncthreads();
    }
}

// ---------------- fused prologue: u + x->fp16, W->fp16, twiddles (one launch) ----------------
__global__ void k_ux(const float* __restrict__ x, const float* __restrict__ w,
                     const float* __restrict__ b0, const float* __restrict__ W) {
    int blk = blockIdx.x;
    int tid = threadIdx.x;       // 128
    if (blk < BB * SS) {
        int r = blk;             // b*S + t
        const float4* xv = reinterpret_cast<const float4*>(x) + (size_t)r * 128;
        const float4* wv = reinterpret_cast<const float4*>(w);
        float4 a = xv[tid], ww = wv[tid];
        half2 h0 = __floats2half2_rn(a.x, a.y);
        half2 h1 = __floats2half2_rn(a.z, a.w);
        uint2 pk;
        pk.x = *reinterpret_cast<uint32_t*>(&h0);
        pk.y = *reinterpret_cast<uint32_t*>(&h1);
        *reinterpret_cast<uint2*>(g_xH + (size_t)r * DD + tid * 4) = pk;
        float p = a.x * ww.x + a.y * ww.y + a.z * ww.z + a.w * ww.w;
        __shared__ float red[128];
        red[tid] = p;
        __syncthreads();
        if (tid < 64) red[tid] += red[tid + 64];
        __syncthreads();
        if (tid < 32) {
            float v = red[tid] + red[tid + 32];
            #pragma unroll
            for (int o = 16; o; o >>= 1) v += __shfl_down_sync(0xffffffffu, v, o);
            if (tid == 0) g_u[r] = fmaxf(v + b0[0], 0.f);
        }
    } else if (blk < BB * SS + 768) {
        size_t i = ((size_t)(blk - BB * SS) * 128 + tid) * 8;
        const float4* src = reinterpret_cast<const float4*>(W + i);
        float4 v0 = src[0], v1 = src[1];
        half2 h[4];
        h[0] = __floats2half2_rn(v0.x, v0.y);
        h[1] = __floats2half2_rn(v0.z, v0.w);
        h[2] = __floats2half2_rn(v1.x, v1.y);
        h[3] = __floats2half2_rn(v1.z, v1.w);
        *reinterpret_cast<uint4*>(g_W16 + i) = *reinterpret_cast<uint4*>(h);
    } else {
        int r = (blk - BB * SS - 768) * 128 + tid;
        float s, c;
        sincosf(-CUDART_PI_F * (float)r / (float)NH, &s, &c);
        g_tw[r] = make_float2(c, s);
    }
}

// ---------------- merged forward FFTs: blocks 0..127 = H pairs, 128..135 = u rows ----------------
__global__ void k_fft_fwd_all(const float* __restrict__ H) {
    extern __shared__ float2 X[];
    int tid = threadIdx.x;
    int blk = blockIdx.x;
    if (blk < 128) {
        const float* h1 = H + (size_t)(2 * blk) * SS;
        const float* h2 = H + (size_t)(2 * blk + 1) * SS;
        for (int j = tid; j < NF; j += 512)
            X[j] = (j < SS) ? make_float2(h1[j], h2[j]) : make_float2(0.f, 0.f);
        __syncthreads();
        fft_fwd_core(X, tid);
        float2* dst = g_Hfft + (size_t)blk * NF;
        for (int j = tid; j < NF; j += 512) dst[j] = X[j];
    } else {
        int b = blk - 128;
        const float* src = g_u + (size_t)b * SS;
        for (int j = tid; j < NF; j += 512)
            X[j] = make_float2(j < SS ? src[j] : 0.f, 0.f);
        __syncthreads();
        fft_fwd_core(X, tid);
        float2* dst = g_Ufft + (size_t)b * NF;
        for (int j = tid; j < NF; j += 512) dst[j] = X[j];
    }
}

// ---------------- product (+ fused stage 1) + inverse FFT; final pass streams to gmem ----------------
__global__ void k_conv() {
    extern __shared__ float2 X[];
    int tid = threadIdx.x;
    int kp = blockIdx.x, b = blockIdx.y;
    const float2* U  = g_Ufft + (size_t)b * NF;
    const float2* Hp = g_Hfft + (size_t)kp * NF;
    for (int t = tid; t < NH; t += 512) {
        int j0 = 2 * t;
        float2 a = cmul(U[j0], Hp[j0]);
        float2 bb = cmul(U[j0 + 1], Hp[j0 + 1]);
        X[j0]     = cadd(a, bb);
        X[j0 + 1] = csub(a, bb);
    }
    __syncthreads();
    fft_inv_core3(X, tid);

    // specialized final pass: m = 1024 (distances 1024/2048/4096), direct output.
    // thread g holds X[g + 1024k]; after the 3 stages, indices g+1024k (k<4) are
    // the natural-order results s < 4096.
    half* d1 = g_mH + ((size_t)b * MEM + 2 * kp) * SS;
    half* d2 = d1 + SS;
    const float inv = 1.f / NF;
    const int m = 1024, st = 4;
    #pragma unroll
    for (int qq = 0; qq < 2; qq++) {
        int g = tid + qq * 512;      // 0..1023
        int jj = g;                  // g & (m-1)
        float2 P[8];
        #pragma unroll
        for (int k = 0; k < 8; k++) P[k] = X[g + k * m];
        float2 wa = g_tw[jj * st];
        float2 w1c = make_float2(wa.x, -wa.y);
        float2 wb = g_tw[jj * (st >> 1)];
        float2 w2c = make_float2(wb.x, -wb.y);
        float2 wc = g_tw[jj * (st >> 2)];
        float2 w4c = make_float2(wc.x, -wc.y);
        #pragma unroll
        for (int base = 0; base < 8; base += 2) {
            float2 t = cmul(P[base + 1], w1c);
            P[base + 1] = csub(P[base], t);
            P[base] = cadd(P[base], t);
        }
        float2 f1 = make_float2(-w2c.y, w2c.x);
        #pragma unroll
        for (int base = 0; base < 8; base += 4) {
            float2 t0 = cmul(P[base + 2], w2c);
            P[base + 2] = csub(P[base], t0);
            P[base] = cadd(P[base], t0);
            float2 t1 = cmul(P[base + 3], f1);
            P[base + 3] = csub(P[base + 1], t1);
            P[base + 1] = cadd(P[base + 1], t1);
        }
        float2 G[4];
        G[0] = w4c;
        G[1] = make_float2(RT2 * (w4c.x - w4c.y), RT2 * (w4c.x + w4c.y));
        G[2] = make_float2(-w4c.y, w4c.x);
        G[3] = make_float2(-RT2 * (w4c.x + w4c.y), RT2 * (w4c.x - w4c.y));
        #pragma unroll
        for (int o = 0; o < 4; o++) {
            float2 t = cmul(P[o + 4], G[o]);
            P[o + 4] = csub(P[o], t);
            P[o] = cadd(P[o], t);
        }
        #pragma unroll
        for (int k = 0; k < 4; k++) {
            int s = g + 1024 * k;
            d1[s] = __float2half_rn(P[k].x * inv);
            d2[s] = __float2half_rn(P[k].y * inv);
        }
    }
}

// ---------------- HMMA GEMM: out[b][s][h] = relu([m | x] . W^T + bias) ----------------
// CTA 128(s) x 128(h), 128 threads, 4 warps (2m x 2n), warp tile 64x64
// kt 0..7: A from g_mH [k][s] (k-major), trans tile, ldmatrix.trans
// kt 8..23: A from g_xH [s][d] (row-major), ldmatrix
// tail output (h[:, -1, :]) fused into the epilogue.
#define PAD 40
#define TSTR 136
#define ABUF 5120
#define KT_TRANS 8
#define KT_TOT 24
__global__ __launch_bounds__(128) void k_gemm(const float* __restrict__ bias,
                                              float* __restrict__ out) {
    __shared__ __align__(16) half As[2][ABUF];
    __shared__ __align__(16) half Bs[2][128][PAD];
    int tid = threadIdx.x;
    int lane = tid & 31, warp = tid >> 5;
    int wm = warp & 1, wn = warp >> 1;
    int s0 = blockIdx.x * 128, h0 = blockIdx.y * 128, b = blockIdx.z;

    const half* Mg = g_mH + (size_t)b * MEM * SS;        // [k][s]
    const half* Xg = g_xH + ((size_t)b * SS + s0) * DD;  // [s][d]
    const half* Bg = g_W16 + (size_t)h0 * KK;
    uint32_t sA = s2u(As), sB = s2u(Bs);

    float acc[4][8][4];
    #pragma unroll
    for (int mi = 0; mi < 4; mi++)
        #pragma unroll
        for (int ni = 0; ni < 8; ni++)
            #pragma unroll
            for (int q = 0; q < 4; q++) acc[mi][ni][q] = 0.f;

    auto load = [&](int kt, int buf) {
        int k0 = kt * 32;
        if (kt < KT_TRANS) {
            #pragma unroll
            for (int j = 0; j < 4; j++) {
                int idx = tid + j * 128;
                int row = idx >> 4, cc = idx & 15;
                uint32_t off = (uint32_t)(buf * ABUF + row * TSTR + cc * 8) * 2;
                const half* pa = Mg + (size_t)(k0 + row) * SS + s0 + cc * 8;
                asm volatile("cp.async.ca.shared.global [%0], [%1], 16;" :: "r"(sA + off), "l"(pa));
            }
        } else {
            #pragma unroll
            for (int j = 0; j < 4; j++) {
                int idx = tid + j * 128;
                int row = idx >> 2, cc = idx & 3;
                uint32_t off = (uint32_t)(buf * ABUF + row * PAD + cc * 8) * 2;
                const half* pa = Xg + (size_t)row * DD + (k0 - 256) + cc * 8;
                asm volatile("cp.async.ca.shared.global [%0], [%1], 16;" :: "r"(sA + off), "l"(pa));
            }
        }
        #pragma unroll
        for (int j = 0; j < 4; j++) {
            int idx = tid + j * 128;
            int row = idx >> 2, cc = idx & 3;
            uint32_t off = ((uint32_t)(buf * 128 + row) * PAD + cc * 8) * 2;
            const half* pb = Bg + (size_t)row * KK + k0 + cc * 8;
            asm volatile("cp.async.ca.shared.global [%0], [%1], 16;" :: "r"(sB + off), "l"(pb));
        }
        asm volatile("cp.async.commit_group;");
    };

    load(0, 0);
    int arow = lane & 15;                         // normal path: m row
    int acol = (lane >> 4) << 3;                  // normal path: k offset
    int tkrow = (lane & 7) + ((lane >> 4) << 3);  // trans path: k row
    int tmcol = lane & 8;                         // trans path: m offset
    int brow = ((lane >> 4) << 3) + (lane & 7);
    int bcol = lane & 8;

    for (int kt = 0; kt < KT_TOT; kt++) {
        int buf = kt & 1;
        if (kt + 1 < KT_TOT) {
            load(kt + 1, buf ^ 1);
            asm volatile("cp.async.wait_group 1;");
        } else {
            asm volatile("cp.async.wait_group 0;");
        }
        __syncthreads();
        #pragma unroll
        for (int ks = 0; ks < 32; ks += 16) {
            uint32_t am[4][4];
            if (kt < KT_TRANS) {
                #pragma unroll
                for (int mi = 0; mi < 4; mi++) {
                    uint32_t a = sA + (uint32_t)(buf * ABUF + (ks + tkrow) * TSTR
                                                 + wm * 64 + mi * 16 + tmcol) * 2;
                    asm volatile("ldmatrix.sync.aligned.m8n8.x4.trans.shared.b16 {%0,%1,%2,%3}, [%4];"
                                 : "=r"(am[mi][0]), "=r"(am[mi][1]), "=r"(am[mi][2]), "=r"(am[mi][3])
                                 : "r"(a));
                }
            } else {
                #pragma unroll
                for (int mi = 0; mi < 4; mi++) {
                    uint32_t a = sA + (uint32_t)(buf * ABUF + (wm * 64 + mi * 16 + arow) * PAD
                                                 + ks + acol) * 2;
                    asm volatile("ldmatrix.sync.aligned.m8n8.x4.shared.b16 {%0,%1,%2,%3}, [%4];"
                                 : "=r"(am[mi][0]), "=r"(am[mi][1]), "=r"(am[mi][2]), "=r"(am[mi][3])
                                 : "r"(a));
                }
            }
            uint32_t bm[4][4];
            #pragma unroll
            for (int p = 0; p < 4; p++) {
                uint32_t a = sB + ((uint32_t)(buf * 128 + wn * 64 + p * 16 + brow) * PAD
                                   + ks + bcol) * 2;
                asm volatile("ldmatrix.sync.aligned.m8n8.x4.shared.b16 {%0,%1,%2,%3}, [%4];"
                             : "=r"(bm[p][0]), "=r"(bm[p][1]), "=r"(bm[p][2]), "=r"(bm[p][3])
                             : "r"(a));
            }
            #pragma unroll
            for (int mi = 0; mi < 4; mi++)
                #pragma unroll
                for (int p = 0; p < 4; p++) {
                    asm volatile(
                        "mma.sync.aligned.m16n8k16.row.col.f32.f16.f16.f32 "
                        "{%0,%1,%2,%3}, {%4,%5,%6,%7}, {%8,%9}, {%0,%1,%2,%3};"
                        : "+f"(acc[mi][2*p][0]), "+f"(acc[mi][2*p][1]),
                          "+f"(acc[mi][2*p][2]), "+f"(acc[mi][2*p][3])
                        : "r"(am[mi][0]), "r"(am[mi][1]), "r"(am[mi][2]), "r"(am[mi][3]),
                          "r"(bm[p][0]), "r"(bm[p][1]));
                    asm volatile(
                        "mma.sync.aligned.m16n8k16.row.col.f32.f16.f16.f32 "
                        "{%0,%1,%2,%3}, {%4,%5,%6,%7}, {%8,%9}, {%0,%1,%2,%3};"
                        : "+f"(acc[mi][2*p+1][0]), "+f"(acc[mi][2*p+1][1]),
                          "+f"(acc[mi][2*p+1][2]), "+f"(acc[mi][2*p+1][3])
                        : "r"(am[mi][0]), "r"(am[mi][1]), "r"(am[mi][2]), "r"(am[mi][3]),
                          "r"(bm[p][2]), "r"(bm[p][3]));
                }
        }
        __syncthreads();
    }

    int r = lane >> 2, c = (lane & 3) * 2;
    #pragma unroll
    for (int mi = 0; mi < 4; mi++)
        #pragma unroll
        for (int ni = 0; ni < 8; ni++) {
            int h = h0 + wn * 64 + ni * 8 + c;
            int s = s0 + wm * 64 + mi * 16 + r;
            float b0v = bias[h], b1v = bias[h + 1];
            size_t o0 = ((size_t)b * SS + s) * HID + h;
            float2 v0 = make_float2(fmaxf(acc[mi][ni][0] + b0v, 0.f),
                                    fmaxf(acc[mi][ni][1] + b1v, 0.f));
            *reinterpret_cast<float2*>(out + o0) = v0;
            float2 v1 = make_float2(fmaxf(acc[mi][ni][2] + b0v, 0.f),
                                    fmaxf(acc[mi][ni][3] + b1v, 0.f));
            *reinterpret_cast<float2*>(out + o0 + 8 * HID) = v1;
            if (s + 8 == SS - 1) {
                // fused tail: h[:, -1, :]
                *reinterpret_cast<float2*>(out + (size_t)BB * SS * HID
                                           + (size_t)b * HID + h) = v1;
            }
        }
}

// ---------------- launch ----------------
extern "C" void kernel_launch(void* const* d_in, const int* in_sizes, int n_in,
                              void* d_out, int out_size) {
    const float* x  = (const float*)d_in[0];   // (8, 4096, 512)
    const float* Wu = (const float*)d_in[1];   // (1, 512)
    const float* bu = (const float*)d_in[2];   // (1,)
    const float* Wh = (const float*)d_in[3];   // (1024, 768)
    const float* bh = (const float*)d_in[4];   // (1024,)
    const float* H  = (const float*)d_in[5];   // (256, 4096)
    float* out = (float*)d_out;

    cudaFuncSetAttribute(k_fft_fwd_all, cudaFuncAttributeMaxDynamicSharedMemorySize, NF * 8);
    cudaFuncSetAttribute(k_conv,        cudaFuncAttributeMaxDynamicSharedMemorySize, NF * 8);

    k_ux<<<BB * SS + 768 + 32, 128>>>(x, Wu, bu, Wh);
    k_fft_fwd_all<<<128 + BB, 512, NF * 8>>>(H);
    k_conv<<<dim3(MEM / 2, BB), 512, NF * 8>>>();
    k_gemm<<<dim3(SS / 128, HID / 128, BB), 128>>>(bh, out);
}

// round 17
// speedup vs baseline: 1.2257x; 1.0471x over previous
#include <cuda_runtime.h>
#include <cuda_fp16.h>
#include <math_constants.h>
#include <cstdint>

#define BB 8
#define SS 4096
#define DD 512
#define MEM 256
#define HID 1024
#define KK 768
#define NF 8192
#define NH 4096          // NF/2

// ---------------- device scratch ----------------
__device__ float  g_u[BB * SS];
__device__ float2 g_Ufft[BB * NF];
__device__ float2 g_Hfft[(MEM / 2) * NF];          // packed pair spectra
__device__ float2 g_tw[NH];
__device__ half   g_mH[(size_t)BB * MEM * SS];     // [b][k][s] fp16 (k < 256)
__device__ half   g_xH[(size_t)BB * SS * DD];      // [b][s][d] fp16
__device__ half   g_W16[(size_t)HID * KK];         // [h][k] fp16

__device__ __forceinline__ uint32_t s2u(const void* p) {
    uint32_t a;
    asm("{ .reg .u64 t; cvta.to.shared.u64 t, %1; cvt.u32.u64 %0, t; }" : "=r"(a) : "l"(p));
    return a;
}

__device__ __forceinline__ float2 cmul(float2 a, float2 b) {
    return make_float2(a.x * b.x - a.y * b.y, a.x * b.y + a.y * b.x);
}
__device__ __forceinline__ float2 cadd(float2 a, float2 b) { return make_float2(a.x + b.x, a.y + b.y); }
__device__ __forceinline__ float2 csub(float2 a, float2 b) { return make_float2(a.x - b.x, a.y - b.y); }

#define RT2 0.70710678118654752f

// ================= radix-2^3 FFT cores (512 threads, X[NF] in smem) =================
__device__ __forceinline__ void fft_fwd_core(float2* X, int tid) {
    #pragma unroll
    for (int p = 0; p < 4; p++) {
        const int m  = 4096 >> (3 * p);
        const int m4 = m >> 2;
        const int st = 4096 / m;
        #pragma unroll
        for (int qq = 0; qq < 2; qq++) {
            int q = tid + qq * 512;
            int jj = q & (m4 - 1);
            int i = (q / m4) * 2 * m + jj;
            float2 P[8];
            #pragma unroll
            for (int k = 0; k < 8; k++) P[k] = X[i + k * m4];
            float2 w1 = g_tw[jj * st];
            float2 w2 = g_tw[jj * st * 2];
            float2 w4 = g_tw[jj * st * 4];
            float2 E[4];
            E[0] = w1;
            E[1] = make_float2(RT2 * (w1.x + w1.y), RT2 * (w1.y - w1.x));
            E[2] = make_float2(w1.y, -w1.x);
            E[3] = make_float2(RT2 * (w1.y - w1.x), -RT2 * (w1.x + w1.y));
            #pragma unroll
            for (int o = 0; o < 4; o++) {
                float2 t = csub(P[o], P[o + 4]);
                P[o] = cadd(P[o], P[o + 4]);
                P[o + 4] = cmul(t, E[o]);
            }
            float2 f1 = make_float2(w2.y, -w2.x);
            #pragma unroll
            for (int base = 0; base < 8; base += 4) {
                float2 t0 = csub(P[base], P[base + 2]);
                P[base] = cadd(P[base], P[base + 2]);
                P[base + 2] = cmul(t0, w2);
                float2 t1 = csub(P[base + 1], P[base + 3]);
                P[base + 1] = cadd(P[base + 1], P[base + 3]);
                P[base + 3] = cmul(t1, f1);
            }
            #pragma unroll
            for (int base = 0; base < 8; base += 2) {
                float2 t = csub(P[base], P[base + 1]);
                P[base] = cadd(P[base], P[base + 1]);
                P[base + 1] = cmul(t, w4);
            }
            #pragma unroll
            for (int k = 0; k < 8; k++) X[i + k * m4] = P[k];
        }
        __syncthreads();
    }
    #pragma unroll
    for (int qq = 0; qq < 8; qq++) {
        int t = tid + qq * 512;
        int i0 = 2 * t;
        float2 a = X[i0], b = X[i0 + 1];
        X[i0]     = cadd(a, b);
        X[i0 + 1] = csub(a, b);
    }
    __syncthreads();
}

// Inverse DIT octet passes m = 2, 16, 128 (distances 2..512); the final
// m=1024 pass (1024/2048/4096) is specialized in k_conv with direct output.
__device__ __forceinline__ void fft_inv_core3(float2* X, int tid) {
    #pragma unroll
    for (int p = 0; p < 3; p++) {
        const int m  = 2 << (3 * p);
        const int st = 4096 / m;
        #pragma unroll
        for (int qq = 0; qq < 2; qq++) {
            int g = tid + qq * 512;
            int jj = g & (m - 1);
            int i = (g / m) * 8 * m + jj;
            float2 P[8];
            #pragma unroll
            for (int k = 0; k < 8; k++) P[k] = X[i + k * m];
            float2 wa = g_tw[jj * st];
            float2 w1c = make_float2(wa.x, -wa.y);
            float2 wb = g_tw[jj * (st >> 1)];
            float2 w2c = make_float2(wb.x, -wb.y);
            float2 wc = g_tw[jj * (st >> 2)];
            float2 w4c = make_float2(wc.x, -wc.y);
            #pragma unroll
            for (int base = 0; base < 8; base += 2) {
                float2 t = cmul(P[base + 1], w1c);
                P[base + 1] = csub(P[base], t);
                P[base] = cadd(P[base], t);
            }
            float2 f1 = make_float2(-w2c.y, w2c.x);
            #pragma unroll
            for (int base = 0; base < 8; base += 4) {
                float2 t0 = cmul(P[base + 2], w2c);
                P[base + 2] = csub(P[base], t0);
                P[base] = cadd(P[base], t0);
                float2 t1 = cmul(P[base + 3], f1);
                P[base + 3] = csub(P[base + 1], t1);
                P[base + 1] = cadd(P[base + 1], t1);
            }
            float2 G[4];
            G[0] = w4c;
            G[1] = make_float2(RT2 * (w4c.x - w4c.y), RT2 * (w4c.x + w4c.y));
            G[2] = make_float2(-w4c.y, w4c.x);
            G[3] = make_float2(-RT2 * (w4c.x + w4c.y), RT2 * (w4c.x - w4c.y));
            #pragma unroll
            for (int o = 0; o < 4; o++) {
                float2 t = cmul(P[o + 4], G[o]);
                P[o + 4] = csub(P[o], t);
                P[o] = cadd(P[o], t);
            }
            #pragma unroll
            for (int k = 0; k < 8; k++) X[i + k * m] = P[k];
        }
        __syncthreads();
    }
}

// ---------------- fused prologue: u + x->fp16, W->fp16, twiddles (one launch) ----------------
__global__ void k_ux(const float* __restrict__ x, const float* __restrict__ w,
                     const float* __restrict__ b0, const float* __restrict__ W) {
    int blk = blockIdx.x;
    int tid = threadIdx.x;       // 128
    if (blk < BB * SS) {
        int r = blk;             // b*S + t
        const float4* xv = reinterpret_cast<const float4*>(x) + (size_t)r * 128;
        const float4* wv = reinterpret_cast<const float4*>(w);
        float4 a = xv[tid], ww = wv[tid];
        half2 h0 = __floats2half2_rn(a.x, a.y);
        half2 h1 = __floats2half2_rn(a.z, a.w);
        uint2 pk;
        pk.x = *reinterpret_cast<uint32_t*>(&h0);
        pk.y = *reinterpret_cast<uint32_t*>(&h1);
        *reinterpret_cast<uint2*>(g_xH + (size_t)r * DD + tid * 4) = pk;
        float p = a.x * ww.x + a.y * ww.y + a.z * ww.z + a.w * ww.w;
        __shared__ float red[128];
        red[tid] = p;
        __syncthreads();
        if (tid < 64) red[tid] += red[tid + 64];
        __syncthreads();
        if (tid < 32) {
            float v = red[tid] + red[tid + 32];
            #pragma unroll
            for (int o = 16; o; o >>= 1) v += __shfl_down_sync(0xffffffffu, v, o);
            if (tid == 0) g_u[r] = fmaxf(v + b0[0], 0.f);
        }
    } else if (blk < BB * SS + 768) {
        size_t i = ((size_t)(blk - BB * SS) * 128 + tid) * 8;
        const float4* src = reinterpret_cast<const float4*>(W + i);
        float4 v0 = src[0], v1 = src[1];
        half2 h[4];
        h[0] = __floats2half2_rn(v0.x, v0.y);
        h[1] = __floats2half2_rn(v0.z, v0.w);
        h[2] = __floats2half2_rn(v1.x, v1.y);
        h[3] = __floats2half2_rn(v1.z, v1.w);
        *reinterpret_cast<uint4*>(g_W16 + i) = *reinterpret_cast<uint4*>(h);
    } else {
        int r = (blk - BB * SS - 768) * 128 + tid;
        float s, c;
        sincosf(-CUDART_PI_F * (float)r / (float)NH, &s, &c);
        g_tw[r] = make_float2(c, s);
    }
}

// ---------------- merged forward FFTs: blocks 0..127 = H pairs, 128..135 = u rows ----------------
__global__ void k_fft_fwd_all(const float* __restrict__ H) {
    extern __shared__ float2 X[];
    int tid = threadIdx.x;
    int blk = blockIdx.x;
    if (blk < 128) {
        const float* h1 = H + (size_t)(2 * blk) * SS;
        const float* h2 = H + (size_t)(2 * blk + 1) * SS;
        for (int j = tid; j < NF; j += 512)
            X[j] = (j < SS) ? make_float2(h1[j], h2[j]) : make_float2(0.f, 0.f);
        __syncthreads();
        fft_fwd_core(X, tid);
        float2* dst = g_Hfft + (size_t)blk * NF;
        for (int j = tid; j < NF; j += 512) dst[j] = X[j];
    } else {
        int b = blk - 128;
        const float* src = g_u + (size_t)b * SS;
        for (int j = tid; j < NF; j += 512)
            X[j] = make_float2(j < SS ? src[j] : 0.f, 0.f);
        __syncthreads();
        fft_fwd_core(X, tid);
        float2* dst = g_Ufft + (size_t)b * NF;
        for (int j = tid; j < NF; j += 512) dst[j] = X[j];
    }
}

// ---------------- product (+ fused stage 1) + inverse FFT; final pass streams to gmem ----------------
__global__ void k_conv() {
    extern __shared__ float2 X[];
    int tid = threadIdx.x;
    int kp = blockIdx.x, b = blockIdx.y;
    const float2* U  = g_Ufft + (size_t)b * NF;
    const float2* Hp = g_Hfft + (size_t)kp * NF;
    for (int t = tid; t < NH; t += 512) {
        int j0 = 2 * t;
        float2 a = cmul(U[j0], Hp[j0]);
        float2 bb = cmul(U[j0 + 1], Hp[j0 + 1]);
        X[j0]     = cadd(a, bb);
        X[j0 + 1] = csub(a, bb);
    }
    __syncthreads();
    fft_inv_core3(X, tid);

    half* d1 = g_mH + ((size_t)b * MEM + 2 * kp) * SS;
    half* d2 = d1 + SS;
    const float inv = 1.f / NF;
    const int m = 1024, st = 4;
    #pragma unroll
    for (int qq = 0; qq < 2; qq++) {
        int g = tid + qq * 512;      // 0..1023
        int jj = g;
        float2 P[8];
        #pragma unroll
        for (int k = 0; k < 8; k++) P[k] = X[g + k * m];
        float2 wa = g_tw[jj * st];
        float2 w1c = make_float2(wa.x, -wa.y);
        float2 wb = g_tw[jj * (st >> 1)];
        float2 w2c = make_float2(wb.x, -wb.y);
        float2 wc = g_tw[jj * (st >> 2)];
        float2 w4c = make_float2(wc.x, -wc.y);
        #pragma unroll
        for (int base = 0; base < 8; base += 2) {
            float2 t = cmul(P[base + 1], w1c);
            P[base + 1] = csub(P[base], t);
            P[base] = cadd(P[base], t);
        }
        float2 f1 = make_float2(-w2c.y, w2c.x);
        #pragma unroll
        for (int base = 0; base < 8; base += 4) {
            float2 t0 = cmul(P[base + 2], w2c);
            P[base + 2] = csub(P[base], t0);
            P[base] = cadd(P[base], t0);
            float2 t1 = cmul(P[base + 3], f1);
            P[base + 3] = csub(P[base + 1], t1);
            P[base + 1] = cadd(P[base + 1], t1);
        }
        float2 G[4];
        G[0] = w4c;
        G[1] = make_float2(RT2 * (w4c.x - w4c.y), RT2 * (w4c.x + w4c.y));
        G[2] = make_float2(-w4c.y, w4c.x);
        G[3] = make_float2(-RT2 * (w4c.x + w4c.y), RT2 * (w4c.x - w4c.y));
        #pragma unroll
        for (int o = 0; o < 4; o++) {
            float2 t = cmul(P[o + 4], G[o]);
            P[o + 4] = csub(P[o], t);
            P[o] = cadd(P[o], t);
        }
        #pragma unroll
        for (int k = 0; k < 4; k++) {
            int s = g + 1024 * k;
            d1[s] = __float2half_rn(P[k].x * inv);
            d2[s] = __float2half_rn(P[k].y * inv);
        }
    }
}

// ---------------- HMMA GEMM: out[b][s][h] = relu([m | x] . W^T + bias) ----------------
// CTA 128(s) x 128(h), 128 threads, 4 warps (2m x 2n), warp tile 64x64, BK=64
// kt 0..3: A from g_mH [k][s] (k-major), trans tile [64k][128s+pad], ldmatrix.trans
// kt 4..11: A from g_xH [s][d] (row-major), tile [128s][64k+pad], ldmatrix
// tail output (h[:, -1, :]) fused into the epilogue. Dynamic smem, 2 CTAs/SM.
#define PADW 72                  // x/B row stride in halfs (64 + 8 pad)
#define TSTR 136                 // trans tile row stride in halfs
#define ABUF 9216                // halfs per stage buffer (max(64*136, 128*72) = 9216)
#define KT_TRANS 4
#define KT_TOT 12
#define GSMEM (4 * ABUF * 2)     // bytes: 2 A stages + 2 B stages
__global__ __launch_bounds__(128) void k_gemm(const float* __restrict__ bias,
                                              float* __restrict__ out) {
    extern __shared__ __align__(16) half smg[];
    int tid = threadIdx.x;
    int lane = tid & 31, warp = tid >> 5;
    int wm = warp & 1, wn = warp >> 1;
    int s0 = blockIdx.x * 128, h0 = blockIdx.y * 128, b = blockIdx.z;

    const half* Mg = g_mH + (size_t)b * MEM * SS;        // [k][s]
    const half* Xg = g_xH + ((size_t)b * SS + s0) * DD;  // [s][d]
    const half* Bg = g_W16 + (size_t)h0 * KK;
    uint32_t sA = s2u(smg);
    uint32_t sB = sA + 2 * ABUF * 2;

    float acc[4][8][4];
    #pragma unroll
    for (int mi = 0; mi < 4; mi++)
        #pragma unroll
        for (int ni = 0; ni < 8; ni++)
            #pragma unroll
            for (int q = 0; q < 4; q++) acc[mi][ni][q] = 0.f;

    auto load = [&](int kt, int buf) {
        int k0 = kt * 64;
        if (kt < KT_TRANS) {
            // A: [64 k-rows][128 s-cols], 16 chunks of 16B per row, 1024 tasks
            #pragma unroll
            for (int j = 0; j < 8; j++) {
                int idx = tid + j * 128;
                int row = idx >> 4, cc = idx & 15;
                uint32_t off = (uint32_t)(buf * ABUF + row * TSTR + cc * 8) * 2;
                const half* pa = Mg + (size_t)(k0 + row) * SS + s0 + cc * 8;
                asm volatile("cp.async.ca.shared.global [%0], [%1], 16;" :: "r"(sA + off), "l"(pa));
            }
        } else {
            // A: [128 s-rows][64 k-cols], 8 chunks of 16B per row, 1024 tasks
            #pragma unroll
            for (int j = 0; j < 8; j++) {
                int idx = tid + j * 128;
                int row = idx >> 3, cc = idx & 7;
                uint32_t off = (uint32_t)(buf * ABUF + row * PADW + cc * 8) * 2;
                const half* pa = Xg + (size_t)row * DD + (k0 - 256) + cc * 8;
                asm volatile("cp.async.ca.shared.global [%0], [%1], 16;" :: "r"(sA + off), "l"(pa));
            }
        }
        // B: [128 h-rows][64 k-cols]
        #pragma unroll
        for (int j = 0; j < 8; j++) {
            int idx = tid + j * 128;
            int row = idx >> 3, cc = idx & 7;
            uint32_t off = (uint32_t)(buf * ABUF + row * PADW + cc * 8) * 2;
            const half* pb = Bg + (size_t)row * KK + k0 + cc * 8;
            asm volatile("cp.async.ca.shared.global [%0], [%1], 16;" :: "r"(sB + off), "l"(pb));
        }
        asm volatile("cp.async.commit_group;");
    };

    load(0, 0);
    int arow = lane & 15;                         // normal path: m row
    int acol = (lane >> 4) << 3;                  // normal path: k offset
    int tkrow = (lane & 7) + ((lane >> 4) << 3);  // trans path: k row
    int tmcol = lane & 8;                         // trans path: m offset
    int brow = ((lane >> 4) << 3) + (lane & 7);
    int bcol = lane & 8;

    for (int kt = 0; kt < KT_TOT; kt++) {
        int buf = kt & 1;
        if (kt + 1 < KT_TOT) {
            load(kt + 1, buf ^ 1);
            asm volatile("cp.async.wait_group 1;");
        } else {
            asm volatile("cp.async.wait_group 0;");
        }
        __syncthreads();
        #pragma unroll
        for (int ks = 0; ks < 64; ks += 16) {
            uint32_t am[4][4];
            if (kt < KT_TRANS) {
                #pragma unroll
                for (int mi = 0; mi < 4; mi++) {
                    uint32_t a = sA + (uint32_t)(buf * ABUF + (ks + tkrow) * TSTR
                                                 + wm * 64 + mi * 16 + tmcol) * 2;
                    asm volatile("ldmatrix.sync.aligned.m8n8.x4.trans.shared.b16 {%0,%1,%2,%3}, [%4];"
                                 : "=r"(am[mi][0]), "=r"(am[mi][1]), "=r"(am[mi][2]), "=r"(am[mi][3])
                                 : "r"(a));
                }
            } else {
                #pragma unroll
                for (int mi = 0; mi < 4; mi++) {
                    uint32_t a = sA + (uint32_t)(buf * ABUF + (wm * 64 + mi * 16 + arow) * PADW
                                                 + ks + acol) * 2;
                    asm volatile("ldmatrix.sync.aligned.m8n8.x4.shared.b16 {%0,%1,%2,%3}, [%4];"
                                 : "=r"(am[mi][0]), "=r"(am[mi][1]), "=r"(am[mi][2]), "=r"(am[mi][3])
                                 : "r"(a));
                }
            }
            uint32_t bm[4][4];
            #pragma unroll
            for (int p = 0; p < 4; p++) {
                uint32_t a = sB + (uint32_t)(buf * ABUF + (wn * 64 + p * 16 + brow) * PADW
                                             + ks + bcol) * 2;
                asm volatile("ldmatrix.sync.aligned.m8n8.x4.shared.b16 {%0,%1,%2,%3}, [%4];"
                             : "=r"(bm[p][0]), "=r"(bm[p][1]), "=r"(bm[p][2]), "=r"(bm[p][3])
                             : "r"(a));
            }
            #pragma unroll
            for (int mi = 0; mi < 4; mi++)
                #pragma unroll
                for (int p = 0; p < 4; p++) {
                    asm volatile(
                        "mma.sync.aligned.m16n8k16.row.col.f32.f16.f16.f32 "
                        "{%0,%1,%2,%3}, {%4,%5,%6,%7}, {%8,%9}, {%0,%1,%2,%3};"
                        : "+f"(acc[mi][2*p][0]), "+f"(acc[mi][2*p][1]),
                          "+f"(acc[mi][2*p][2]), "+f"(acc[mi][2*p][3])
                        : "r"(am[mi][0]), "r"(am[mi][1]), "r"(am[mi][2]), "r"(am[mi][3]),
                          "r"(bm[p][0]), "r"(bm[p][1]));
                    asm volatile(
                        "mma.sync.aligned.m16n8k16.row.col.f32.f16.f16.f32 "
                        "{%0,%1,%2,%3}, {%4,%5,%6,%7}, {%8,%9}, {%0,%1,%2,%3};"
                        : "+f"(acc[mi][2*p+1][0]), "+f"(acc[mi][2*p+1][1]),
                          "+f"(acc[mi][2*p+1][2]), "+f"(acc[mi][2*p+1][3])
                        : "r"(am[mi][0]), "r"(am[mi][1]), "r"(am[mi][2]), "r"(am[mi][3]),
                          "r"(bm[p][2]), "r"(bm[p][3]));
                }
        }
        __syncthreads();
    }

    int r = lane >> 2, c = (lane & 3) * 2;
    #pragma unroll
    for (int mi = 0; mi < 4; mi++)
        #pragma unroll
        for (int ni = 0; ni < 8; ni++) {
            int h = h0 + wn * 64 + ni * 8 + c;
            int s = s0 + wm * 64 + mi * 16 + r;
            float b0v = bias[h], b1v = bias[h + 1];
            size_t o0 = ((size_t)b * SS + s) * HID + h;
            float2 v0 = make_float2(fmaxf(acc[mi][ni][0] + b0v, 0.f),
                                    fmaxf(acc[mi][ni][1] + b1v, 0.f));
            *reinterpret_cast<float2*>(out + o0) = v0;
            float2 v1 = make_float2(fmaxf(acc[mi][ni][2] + b0v, 0.f),
                                    fmaxf(acc[mi][ni][3] + b1v, 0.f));
            *reinterpret_cast<float2*>(out + o0 + 8 * HID) = v1;
            if (s + 8 == SS - 1) {
                *reinterpret_cast<float2*>(out + (size_t)BB * SS * HID
                                           + (size_t)b * HID + h) = v1;
            }
        }
}

// ---------------- launch ----------------
extern "C" void kernel_launch(void* const* d_in, const int* in_sizes, int n_in,
                              void* d_out, int out_size) {
    const float* x  = (const float*)d_in[0];   // (8, 4096, 512)
    const float* Wu = (const float*)d_in[1];   // (1, 512)
    const float* bu = (const float*)d_in[2];   // (1,)
    const float* Wh = (const float*)d_in[3];   // (1024, 768)
    const float* bh = (const float*)d_in[4];   // (1024,)
    const float* H  = (const float*)d_in[5];   // (256, 4096)
    float* out = (float*)d_out;

    cudaFuncSetAttribute(k_fft_fwd_all, cudaFuncAttributeMaxDynamicSharedMemorySize, NF * 8);
    cudaFuncSetAttribute(k_conv,        cudaFuncAttributeMaxDynamicSharedMemorySize, NF * 8);
    cudaFuncSetAttribute(k_gemm,        cudaFuncAttributeMaxDynamicSharedMemorySize, GSMEM);

    k_ux<<<BB * SS + 768 + 32, 128>>>(x, Wu, bu, Wh);
    k_fft_fwd_all<<<128 + BB, 512, NF * 8>>>(H);
    k_conv<<<dim3(MEM / 2, BB), 512, NF * 8>>>();
    k_gemm<<<dim3(SS / 128, HID / 128, BB), 128, GSMEM>>>(bh, out);
}